// round 14
// baseline (speedup 1.0000x reference)
#include <cuda_runtime.h>
#include <cuda_bf16.h>
#include <math.h>
#include <cstdint>

#define B_  4
#define C_  256
#define CQ_ 32
#define N_  4096

typedef unsigned int u32;
typedef unsigned long long u64;

// bf16 scratch: Q/K [b][n][32]; V channel-major [b][c][n]
__device__ __align__(256) __nv_bfloat16 g_Qh[(size_t)B_ * N_ * CQ_];
__device__ __align__(256) __nv_bfloat16 g_Kh[(size_t)B_ * N_ * CQ_];
__device__ __align__(256) __nv_bfloat16 g_Vh[(size_t)B_ * C_ * N_];

__device__ __forceinline__ u32 smem_u32(const void* p) {
    u32 a; asm("{ .reg .u64 t; cvta.to.shared.u64 t, %1; cvt.u32.u64 %0, t; }"
               : "=r"(a) : "l"(p)); return a;
}
__device__ __forceinline__ u32 bf2pack(float lo, float hi) {
    u32 r;
    asm("{ .reg .b16 a,b; cvt.rn.bf16.f32 a,%1; cvt.rn.bf16.f32 b,%2; mov.b32 %0,{a,b}; }"
        : "=r"(r) : "f"(lo), "f"(hi));
    return r;
}
__device__ __forceinline__ u64 pack2(float lo, float hi) {
    u64 r; asm("mov.b64 %0,{%1,%2};" : "=l"(r) : "f"(lo), "f"(hi)); return r;
}
__device__ __forceinline__ void unpack2(u64 v, float& lo, float& hi) {
    asm("mov.b64 {%0,%1},%2;" : "=f"(lo), "=f"(hi) : "l"(v));
}
__device__ __forceinline__ u64 fma2(u64 a, u64 b, u64 c) {
    u64 d; asm("fma.rn.f32x2 %0,%1,%2,%3;" : "=l"(d) : "l"(a), "l"(b), "l"(c)); return d;
}
__device__ __forceinline__ void mma16(float* d, const u32* a, u32 b0, u32 b1) {
    asm volatile("mma.sync.aligned.m16n8k16.row.col.f32.bf16.bf16.f32 "
        "{%0,%1,%2,%3},{%4,%5,%6,%7},{%8,%9},{%0,%1,%2,%3};"
        : "+f"(d[0]), "+f"(d[1]), "+f"(d[2]), "+f"(d[3])
        : "r"(a[0]), "r"(a[1]), "r"(a[2]), "r"(a[3]), "r"(b0), "r"(b1));
}
__device__ __forceinline__ void ldsm4(u32& r0, u32& r1, u32& r2, u32& r3, u32 addr) {
    asm volatile("ldmatrix.sync.aligned.m8n8.x4.shared.b16 {%0,%1,%2,%3},[%4];"
                 : "=r"(r0), "=r"(r1), "=r"(r2), "=r"(r3) : "r"(addr));
}
#define CP16(dst, src) \
    asm volatile("cp.async.cg.shared.global [%0],[%1],16;" :: "r"(dst), "l"(src) : "memory")
#define CP_COMMIT() asm volatile("cp.async.commit_group;" ::: "memory")
#define CP_WAIT0()  asm volatile("cp.async.wait_group 0;" ::: "memory")

// ---------------------------------------------------------------------------
// Kernel 1: QKV projection — R12 structure, inner loop on packed f32x2
// (pixel pairs; f32x2 instruction proven in R2's passing kernel).
// ---------------------------------------------------------------------------
__global__ void __launch_bounds__(256) proj_kernel(
    const float* __restrict__ x, const float* __restrict__ mask,
    const float* __restrict__ Wq, const float* __restrict__ bq,
    const float* __restrict__ Wk, const float* __restrict__ bk,
    const float* __restrict__ Wv, const float* __restrict__ bv)
{
    __shared__ float xs[64 * 64];
    __shared__ float wsT[64 * 65];

    const int tid = threadIdx.x;
    const int tx = tid & 15, ty = tid >> 4;
    const int pix0 = blockIdx.x * 64;
    const int g = blockIdx.y;
    const int b = blockIdx.z;

    u64 acc2[2][4];     // [p2][rr]: pixels ty*4+2*p2, ty*4+2*p2+1
#pragma unroll
    for (int i = 0; i < 2; i++)
#pragma unroll
        for (int j = 0; j < 4; j++) acc2[i][j] = 0ULL;

    for (int ch = 0; ch < 4; ch++) {
        const int c0 = ch * 64;
        __syncthreads();
        {
            const float4* X4 = (const float4*)x;
            float4* xs4 = (float4*)xs;
#pragma unroll
            for (int it = 0; it < 4; it++) {
                int e4 = tid + it * 256;
                int cc = e4 >> 4, p4 = e4 & 15;
                xs4[cc * 16 + p4] =
                    X4[(size_t)(b * C_ + c0 + cc) * (N_ / 4) + (pix0 >> 2) + p4];
            }
        }
        {
#pragma unroll
            for (int it = 0; it < 4; it++) {
                int e4 = tid + it * 256;
                int o = e4 >> 4, c4 = e4 & 15;
                const float* wrow;
                if (g == 0) wrow = (o < 32) ? (Wq + o * C_) : (Wk + (o - 32) * C_);
                else        wrow = Wv + ((g - 1) * 64 + o) * C_;
                float4 w4 = *(const float4*)(wrow + c0 + c4 * 4);
                wsT[(c4 * 4 + 0) * 65 + o] = w4.x;
                wsT[(c4 * 4 + 1) * 65 + o] = w4.y;
                wsT[(c4 * 4 + 2) * 65 + o] = w4.z;
                wsT[(c4 * 4 + 3) * 65 + o] = w4.w;
            }
        }
        __syncthreads();
        const u64* xs2 = (const u64*)xs;
#pragma unroll 8
        for (int cc = 0; cc < 64; cc++) {
            u64 xr0 = xs2[cc * 32 + ty * 2];
            u64 xr1 = xs2[cc * 32 + ty * 2 + 1];
#pragma unroll
            for (int rr = 0; rr < 4; rr++) {
                float wv = wsT[cc * 65 + tx + 16 * rr];
                u64 w2 = pack2(wv, wv);
                acc2[0][rr] = fma2(xr0, w2, acc2[0][rr]);
                acc2[1][rr] = fma2(xr1, w2, acc2[1][rr]);
            }
        }
    }

    float acc[4][4];
#pragma unroll
    for (int p2 = 0; p2 < 2; p2++)
#pragma unroll
        for (int rr = 0; rr < 4; rr++)
            unpack2(acc2[p2][rr], acc[2 * p2][rr], acc[2 * p2 + 1][rr]);

    if (g == 0) {
#pragma unroll
        for (int pp = 0; pp < 4; pp++) {
            int p = ty * 4 + pp;
            float mv = mask[(b << 12) + pix0 + p];
#pragma unroll
            for (int rr = 0; rr < 4; rr++) {
                int o = tx + 16 * rr;
                if (o < 32) {
                    g_Qh[((size_t)(b << 12) + pix0 + p) * CQ_ + o] =
                        __float2bfloat16_rn((acc[pp][rr] + bq[o]) * mv);
                } else {
                    g_Kh[((size_t)(b << 12) + pix0 + p) * CQ_ + (o - 32)] =
                        __float2bfloat16_rn((acc[pp][rr] + bk[o - 32]) * mv);
                }
            }
        }
    } else {
#pragma unroll
        for (int pp = 0; pp < 4; pp++) {
            int p = ty * 4 + pp;
#pragma unroll
            for (int rr = 0; rr < 4; rr++) {
                int vo = (g - 1) * 64 + tx + 16 * rr;
                g_Vh[(((size_t)(b * C_ + vo)) << 12) + pix0 + p] =
                    __float2bfloat16_rn(acc[pp][rr] + bv[vo]);
            }
        }
    }
}

// ---------------------------------------------------------------------------
// Kernel 2: full-tensor flash attention, 128 queries/CTA, grid (32,B) = 128
// CTAs (<=1 per SM, balanced wave). Each warp owns rows [16w,16w+16) for
// S + softmax + PV (alpha/l in registers; P warp-private -> 1 sync/tile).
// All mma/ldsm blocks are R12-proven patterns, only row/chan counts change.
// smem: Q[128x80B] | K0,K1[64x80B] | V0,V1[256x144B] | P[128x144B]
// ---------------------------------------------------------------------------
#define QOFF_B  0
#define K0_B    10240
#define K1_B    15360
#define V0_B    20480
#define V1_B    57344
#define P_B     94208
#define A_SMEM_BYTES 112640

__global__ void __launch_bounds__(256)
attn_kernel(const float* __restrict__ x, const float* __restrict__ gamma,
            float* __restrict__ out)
{
    extern __shared__ float sm[];
    char* smem8 = (char*)sm;
    const u32 sb = smem_u32(sm);

    const int tid = threadIdx.x;
    const int w = tid >> 5, l = tid & 31;
    const int kq = l & 3, rloc = l >> 2;
    const int b = blockIdx.y;
    const int i0 = blockIdx.x * 128;

    const uint4* Q4g = (const uint4*)g_Qh;
    const uint4* K4g = (const uint4*)g_Kh;
    const uint4* V4g = (const uint4*)g_Vh;

    // ---- prologue: stage Q; cp.async K0 + V0 ----
    {
#pragma unroll
        for (int it = 0; it < 2; it++) {
            int e = tid + it * 256;
            int row = e >> 2, c = e & 3;
            *(uint4*)(smem8 + QOFF_B + row * 80 + c * 16) =
                Q4g[((size_t)((b << 12) + i0 + row)) * 4 + c];
        }
        int row = tid >> 2, c = tid & 3;
        CP16(sb + K0_B + row * 80 + c * 16,
             K4g + ((size_t)(b << 12) + row) * 4 + c);
#pragma unroll
        for (int it = 0; it < 8; it++) {
            int e = tid + it * 256;
            int chn = e >> 3, cc = e & 7;
            CP16(sb + V0_B + chn * 144 + cc * 16,
                 V4g + (((size_t)(b * C_ + chn)) << 9) + cc);
        }
        CP_COMMIT();
    }
    __syncthreads();

    // Q A-frags for this warp's 16 rows (R12 pattern, stride 40h)
    u32 qa[2][4];
#pragma unroll
    for (int kc = 0; kc < 2; kc++)
        ldsm4(qa[kc][0], qa[kc][1], qa[kc][2], qa[kc][3],
              sb + QOFF_B + ((16 * w + (l & 15)) * 40 + kc * 16 + (l >> 4) * 8) * 2);

    float oacc[32][4];
#pragma unroll
    for (int nt = 0; nt < 32; nt++)
#pragma unroll
        for (int i = 0; i < 4; i++) oacc[nt][i] = 0.f;
    float m0 = -INFINITY, m1 = -INFINITY, l0s = 0.f, l1s = 0.f;

    const u32 pw = P_B + w * 0;      // P rows are addressed by global row below

    for (int t = 0; t < 64; t++) {
        CP_WAIT0();
        __syncthreads();            // K[t],V[t] resident for all threads

        if (t + 1 < 64) {
            const u32 kd = sb + (((t + 1) & 1) ? K1_B : K0_B);
            const u32 vd = sb + (((t + 1) & 1) ? V1_B : V0_B);
            int row = tid >> 2, c = tid & 3;
            CP16(kd + row * 80 + c * 16,
                 K4g + ((size_t)((b << 12) + (t + 1) * 64 + row)) * 4 + c);
#pragma unroll
            for (int it = 0; it < 8; it++) {
                int e = tid + it * 256;
                int chn = e >> 3, cc = e & 7;
                CP16(vd + chn * 144 + cc * 16,
                     V4g + (((size_t)(b * C_ + chn)) << 9) + (t + 1) * 8 + cc);
            }
            CP_COMMIT();
        }

        // ---- S = Q K^T (R12-proven ldsm/mma pattern; all 8 warps) ----
        const u32 kB = sb + ((t & 1) ? K1_B : K0_B);
        float s[8][4];
#pragma unroll
        for (int nt = 0; nt < 8; nt++)
#pragma unroll
            for (int i = 0; i < 4; i++) s[nt][i] = 0.f;
#pragma unroll
        for (int kc = 0; kc < 2; kc++) {
#pragma unroll
            for (int np = 0; np < 4; np++) {
                u32 k0, k1, k2, k3;
                ldsm4(k0, k1, k2, k3,
                      kB + ((16 * np + (l & 7) + ((l >> 4) & 1) * 8) * 40
                            + kc * 16 + ((l >> 3) & 1) * 8) * 2);
                mma16(s[2 * np],     qa[kc], k0, k1);
                mma16(s[2 * np + 1], qa[kc], k2, k3);
            }
        }

        // ---- online softmax (rows 16w+rloc, +8); alpha stays in regs ----
        float rm0 = -INFINITY, rm1 = -INFINITY;
#pragma unroll
        for (int nt = 0; nt < 8; nt++) {
            rm0 = fmaxf(rm0, fmaxf(s[nt][0], s[nt][1]));
            rm1 = fmaxf(rm1, fmaxf(s[nt][2], s[nt][3]));
        }
        rm0 = fmaxf(rm0, __shfl_xor_sync(0xffffffffu, rm0, 1));
        rm0 = fmaxf(rm0, __shfl_xor_sync(0xffffffffu, rm0, 2));
        rm1 = fmaxf(rm1, __shfl_xor_sync(0xffffffffu, rm1, 1));
        rm1 = fmaxf(rm1, __shfl_xor_sync(0xffffffffu, rm1, 2));
        float mn0 = fmaxf(m0, rm0), mn1 = fmaxf(m1, rm1);
        float al0 = __expf(m0 - mn0), al1 = __expf(m1 - mn1);
        m0 = mn0; m1 = mn1;
        float ps0 = 0.f, ps1 = 0.f;
#pragma unroll
        for (int nt = 0; nt < 8; nt++) {
            s[nt][0] = __expf(s[nt][0] - mn0);
            s[nt][1] = __expf(s[nt][1] - mn0);
            s[nt][2] = __expf(s[nt][2] - mn1);
            s[nt][3] = __expf(s[nt][3] - mn1);
            ps0 += s[nt][0] + s[nt][1];
            ps1 += s[nt][2] + s[nt][3];
        }
        ps0 += __shfl_xor_sync(0xffffffffu, ps0, 1);
        ps0 += __shfl_xor_sync(0xffffffffu, ps0, 2);
        ps1 += __shfl_xor_sync(0xffffffffu, ps1, 1);
        ps1 += __shfl_xor_sync(0xffffffffu, ps1, 2);
        l0s = l0s * al0 + ps0;
        l1s = l1s * al1 + ps1;

        if (!__all_sync(0xffffffffu, (al0 == 1.f) && (al1 == 1.f))) {
#pragma unroll
            for (int nt = 0; nt < 32; nt++) {
                oacc[nt][0] *= al0; oacc[nt][1] *= al0;
                oacc[nt][2] *= al1; oacc[nt][3] *= al1;
            }
        }

        // ---- P store (D-layout addressing, R12-proven), warp-private ----
#pragma unroll
        for (int nt = 0; nt < 8; nt++) {
            *(u32*)(smem8 + P_B + ((16 * w + rloc) * 72 + 8 * nt + 2 * kq) * 2) =
                bf2pack(s[nt][0], s[nt][1]);
            *(u32*)(smem8 + P_B + ((16 * w + rloc + 8) * 72 + 8 * nt + 2 * kq) * 2) =
                bf2pack(s[nt][2], s[nt][3]);
        }
        __syncwarp();               // producer == consumer warp

        // ---- PV (R12-proven pattern; this warp's rows x all 256 chans) ----
        {
            u32 pa[4][4];
#pragma unroll
            for (int kc = 0; kc < 4; kc++)
                ldsm4(pa[kc][0], pa[kc][1], pa[kc][2], pa[kc][3],
                      sb + P_B + ((16 * w + (l & 15)) * 72 + kc * 16 + (l >> 4) * 8) * 2);
            const u32 vB = sb + ((t & 1) ? V1_B : V0_B);
#pragma unroll
            for (int kc = 0; kc < 4; kc++) {
#pragma unroll
                for (int np = 0; np < 16; np++) {
                    u32 v0, v1, v2, v3;
                    ldsm4(v0, v1, v2, v3,
                          vB + ((16 * np + (l & 7) + ((l >> 4) & 1) * 8) * 72
                                + kc * 16 + ((l >> 3) & 1) * 8) * 2);
                    mma16(oacc[2 * np],     pa[kc], v0, v1);
                    mma16(oacc[2 * np + 1], pa[kc], v2, v3);
                }
            }
        }
        __syncwarp();               // P reads done before next-iter stores
    }

    // ---- epilogue: out = gamma*O/l + x; two 128-chan phases ----
    const float gm = gamma[0];
    const float g0 = gm / l0s, g1 = gm / l1s;
    const int row0 = 16 * w + rloc, row1 = row0 + 8;
    float* ts = sm;                 // [cl][row] stride 132, 128 rows
#pragma unroll 1
    for (int ph = 0; ph < 2; ph++) {
        __syncthreads();
#pragma unroll
        for (int npl = 0; npl < 8; npl++) {
            int np = 8 * ph + npl;
            int cl0 = 16 * npl + 2 * kq;
            int cl1 = 16 * npl + 8 + 2 * kq;
            ts[cl0 * 132 + row0]       = oacc[2 * np][0] * g0;
            ts[(cl0 + 1) * 132 + row0] = oacc[2 * np][1] * g0;
            ts[cl0 * 132 + row1]       = oacc[2 * np][2] * g1;
            ts[(cl0 + 1) * 132 + row1] = oacc[2 * np][3] * g1;
            ts[cl1 * 132 + row0]       = oacc[2 * np + 1][0] * g0;
            ts[(cl1 + 1) * 132 + row0] = oacc[2 * np + 1][1] * g0;
            ts[cl1 * 132 + row1]       = oacc[2 * np + 1][2] * g1;
            ts[(cl1 + 1) * 132 + row1] = oacc[2 * np + 1][3] * g1;
        }
        __syncthreads();
#pragma unroll
        for (int it = 0; it < 16; it++) {
            int e = tid + it * 256;
            int c = e >> 5, r4 = e & 31;
            float4 o4 = *(const float4*)(ts + c * 132 + r4 * 4);
            size_t g4 = (size_t)(b * C_ + ph * 128 + c) * 1024 + (i0 >> 2) + r4;
            float4 x4 = ((const float4*)x)[g4];
            o4.x += x4.x; o4.y += x4.y; o4.z += x4.z; o4.w += x4.w;
            ((float4*)out)[g4] = o4;
        }
    }
}

// ---------------------------------------------------------------------------
extern "C" void kernel_launch(void* const* d_in, const int* in_sizes, int n_in,
                              void* d_out, int out_size)
{
    const float* x     = (const float*)d_in[0];
    const float* mask  = (const float*)d_in[1];
    const float* Wq    = (const float*)d_in[2];
    const float* bq    = (const float*)d_in[3];
    const float* Wk    = (const float*)d_in[4];
    const float* bk    = (const float*)d_in[5];
    const float* Wv    = (const float*)d_in[6];
    const float* bv    = (const float*)d_in[7];
    const float* gamma = (const float*)d_in[8];
    float* out = (float*)d_out;

    cudaFuncSetAttribute(attn_kernel,
                         cudaFuncAttributeMaxDynamicSharedMemorySize, A_SMEM_BYTES);

    dim3 pgrid(N_ / 64, 5, B_);
    proj_kernel<<<pgrid, 256>>>(x, mask, Wq, bq, Wk, bk, Wv, bv);

    dim3 agrid(N_ / 128, B_);
    attn_kernel<<<agrid, 256, A_SMEM_BYTES>>>(x, gamma, out);
}

// round 15
// speedup vs baseline: 3.2472x; 3.2472x over previous
#include <cuda_runtime.h>
#include <cuda_bf16.h>
#include <math.h>
#include <cstdint>

#define B_  4
#define C_  256
#define CQ_ 32
#define N_  4096

typedef unsigned int u32;
typedef unsigned long long u64;

// bf16 scratch: Q/K [b][n][32]; V channel-major [b][c][n]
__device__ __align__(256) __nv_bfloat16 g_Qh[(size_t)B_ * N_ * CQ_];
__device__ __align__(256) __nv_bfloat16 g_Kh[(size_t)B_ * N_ * CQ_];
__device__ __align__(256) __nv_bfloat16 g_Vh[(size_t)B_ * C_ * N_];

__device__ __forceinline__ u32 smem_u32(const void* p) {
    u32 a; asm("{ .reg .u64 t; cvta.to.shared.u64 t, %1; cvt.u32.u64 %0, t; }"
               : "=r"(a) : "l"(p)); return a;
}
__device__ __forceinline__ u32 bf2pack(float lo, float hi) {
    u32 r;
    asm("{ .reg .b16 a,b; cvt.rn.bf16.f32 a,%1; cvt.rn.bf16.f32 b,%2; mov.b32 %0,{a,b}; }"
        : "=r"(r) : "f"(lo), "f"(hi));
    return r;
}
__device__ __forceinline__ u64 pack2(float lo, float hi) {
    u64 r; asm("mov.b64 %0,{%1,%2};" : "=l"(r) : "f"(lo), "f"(hi)); return r;
}
__device__ __forceinline__ void unpack2(u64 v, float& lo, float& hi) {
    asm("mov.b64 {%0,%1},%2;" : "=f"(lo), "=f"(hi) : "l"(v));
}
__device__ __forceinline__ u64 fma2(u64 a, u64 b, u64 c) {
    u64 d; asm("fma.rn.f32x2 %0,%1,%2,%3;" : "=l"(d) : "l"(a), "l"(b), "l"(c)); return d;
}
__device__ __forceinline__ void mma16(float* d, const u32* a, u32 b0, u32 b1) {
    asm volatile("mma.sync.aligned.m16n8k16.row.col.f32.bf16.bf16.f32 "
        "{%0,%1,%2,%3},{%4,%5,%6,%7},{%8,%9},{%0,%1,%2,%3};"
        : "+f"(d[0]), "+f"(d[1]), "+f"(d[2]), "+f"(d[3])
        : "r"(a[0]), "r"(a[1]), "r"(a[2]), "r"(a[3]), "r"(b0), "r"(b1));
}
__device__ __forceinline__ void ldsm4(u32& r0, u32& r1, u32& r2, u32& r3, u32 addr) {
    asm volatile("ldmatrix.sync.aligned.m8n8.x4.shared.b16 {%0,%1,%2,%3},[%4];"
                 : "=r"(r0), "=r"(r1), "=r"(r2), "=r"(r3) : "r"(addr));
}
#define CP16(dst, src) \
    asm volatile("cp.async.cg.shared.global [%0],[%1],16;" :: "r"(dst), "l"(src) : "memory")
#define CP_COMMIT() asm volatile("cp.async.commit_group;" ::: "memory")
#define CP_WAIT0()  asm volatile("cp.async.wait_group 0;" ::: "memory")

// ---------------------------------------------------------------------------
// Kernel 1: QKV projection — R12/R14 structure, packed f32x2 inner loop.
// ---------------------------------------------------------------------------
__global__ void __launch_bounds__(256) proj_kernel(
    const float* __restrict__ x, const float* __restrict__ mask,
    const float* __restrict__ Wq, const float* __restrict__ bq,
    const float* __restrict__ Wk, const float* __restrict__ bk,
    const float* __restrict__ Wv, const float* __restrict__ bv)
{
    __shared__ float xs[64 * 64];
    __shared__ float wsT[64 * 65];

    const int tid = threadIdx.x;
    const int tx = tid & 15, ty = tid >> 4;
    const int pix0 = blockIdx.x * 64;
    const int g = blockIdx.y;
    const int b = blockIdx.z;

    u64 acc2[2][4];
#pragma unroll
    for (int i = 0; i < 2; i++)
#pragma unroll
        for (int j = 0; j < 4; j++) acc2[i][j] = 0ULL;

    for (int ch = 0; ch < 4; ch++) {
        const int c0 = ch * 64;
        __syncthreads();
        {
            const float4* X4 = (const float4*)x;
            float4* xs4 = (float4*)xs;
#pragma unroll
            for (int it = 0; it < 4; it++) {
                int e4 = tid + it * 256;
                int cc = e4 >> 4, p4 = e4 & 15;
                xs4[cc * 16 + p4] =
                    X4[(size_t)(b * C_ + c0 + cc) * (N_ / 4) + (pix0 >> 2) + p4];
            }
        }
        {
#pragma unroll
            for (int it = 0; it < 4; it++) {
                int e4 = tid + it * 256;
                int o = e4 >> 4, c4 = e4 & 15;
                const float* wrow;
                if (g == 0) wrow = (o < 32) ? (Wq + o * C_) : (Wk + (o - 32) * C_);
                else        wrow = Wv + ((g - 1) * 64 + o) * C_;
                float4 w4 = *(const float4*)(wrow + c0 + c4 * 4);
                wsT[(c4 * 4 + 0) * 65 + o] = w4.x;
                wsT[(c4 * 4 + 1) * 65 + o] = w4.y;
                wsT[(c4 * 4 + 2) * 65 + o] = w4.z;
                wsT[(c4 * 4 + 3) * 65 + o] = w4.w;
            }
        }
        __syncthreads();
        const u64* xs2 = (const u64*)xs;
#pragma unroll 8
        for (int cc = 0; cc < 64; cc++) {
            u64 xr0 = xs2[cc * 32 + ty * 2];
            u64 xr1 = xs2[cc * 32 + ty * 2 + 1];
#pragma unroll
            for (int rr = 0; rr < 4; rr++) {
                float wv = wsT[cc * 65 + tx + 16 * rr];
                u64 w2 = pack2(wv, wv);
                acc2[0][rr] = fma2(xr0, w2, acc2[0][rr]);
                acc2[1][rr] = fma2(xr1, w2, acc2[1][rr]);
            }
        }
    }

    float acc[4][4];
#pragma unroll
    for (int p2 = 0; p2 < 2; p2++)
#pragma unroll
        for (int rr = 0; rr < 4; rr++)
            unpack2(acc2[p2][rr], acc[2 * p2][rr], acc[2 * p2 + 1][rr]);

    if (g == 0) {
#pragma unroll
        for (int pp = 0; pp < 4; pp++) {
            int p = ty * 4 + pp;
            float mv = mask[(b << 12) + pix0 + p];
#pragma unroll
            for (int rr = 0; rr < 4; rr++) {
                int o = tx + 16 * rr;
                if (o < 32) {
                    g_Qh[((size_t)(b << 12) + pix0 + p) * CQ_ + o] =
                        __float2bfloat16_rn((acc[pp][rr] + bq[o]) * mv);
                } else {
                    g_Kh[((size_t)(b << 12) + pix0 + p) * CQ_ + (o - 32)] =
                        __float2bfloat16_rn((acc[pp][rr] + bk[o - 32]) * mv);
                }
            }
        }
    } else {
#pragma unroll
        for (int pp = 0; pp < 4; pp++) {
            int p = ty * 4 + pp;
#pragma unroll
            for (int rr = 0; rr < 4; rr++) {
                int vo = (g - 1) * 64 + tx + 16 * rr;
                g_Vh[(((size_t)(b * C_ + vo)) << 12) + pix0 + p] =
                    __float2bfloat16_rn(acc[pp][rr] + bv[vo]);
            }
        }
    }
}

// ---------------------------------------------------------------------------
// Kernel 2: flash attention, 128 q/CTA, grid (32,B)=128 CTAs, 512 threads.
// Warp w: rows [16(w&7),16(w&7)+16), channel half (w>>3)*128. Warp pairs
// (w, w+8) recompute S+softmax redundantly -> zero cross-warp comms, P in
// per-warp private smem regions, alpha/l in regs, 1 syncthreads/tile.
// oacc[16][4] = R12-proven register budget (128 regs/thread cap).
// smem: Q[128x80B] | K0,K1[64x80B] | V0,V1[256x144B] | P[16x16x144B] = 128KB
// ---------------------------------------------------------------------------
#define QOFF_B  0
#define K0_B    10240
#define K1_B    15360
#define V0_B    20480
#define V1_B    57344
#define P_B     94208
#define A_SMEM_BYTES 131072

__global__ void __launch_bounds__(512, 1)
attn_kernel(const float* __restrict__ x, const float* __restrict__ gamma,
            float* __restrict__ out)
{
    extern __shared__ float sm[];
    char* smem8 = (char*)sm;
    const u32 sb = smem_u32(sm);

    const int tid = threadIdx.x;
    const int w = tid >> 5, l = tid & 31;
    const int kq = l & 3, rloc = l >> 2;
    const int rg = w & 7;                  // row group: rows [16rg, 16rg+16)
    const int chh = w >> 3;                // channel half
    const int cb = chh * 128;              // channel base
    const int b = blockIdx.y;
    const int i0 = blockIdx.x * 128;

    const uint4* Q4g = (const uint4*)g_Qh;
    const uint4* K4g = (const uint4*)g_Kh;
    const uint4* V4g = (const uint4*)g_Vh;

    // ---- prologue: stage Q; cp.async K0 + V0 ----
    {
        int row = tid >> 2, c = tid & 3;                 // 128 rows x 4 chunks
        *(uint4*)(smem8 + QOFF_B + row * 80 + c * 16) =
            Q4g[((size_t)((b << 12) + i0 + row)) * 4 + c];
        if (tid < 256) {
            int kr = tid >> 2, kc = tid & 3;             // 64 rows x 4 chunks
            CP16(sb + K0_B + kr * 80 + kc * 16,
                 K4g + ((size_t)(b << 12) + kr) * 4 + kc);
        }
#pragma unroll
        for (int it = 0; it < 4; it++) {                 // 256 chans x 8 chunks
            int e = tid + it * 512;
            int chn = e >> 3, cc = e & 7;
            CP16(sb + V0_B + chn * 144 + cc * 16,
                 V4g + (((size_t)(b * C_ + chn)) << 9) + cc);
        }
        CP_COMMIT();
    }
    __syncthreads();

    // Q A-frags for this warp's 16 rows (R12-proven pattern, stride 40h)
    u32 qa[2][4];
#pragma unroll
    for (int kc = 0; kc < 2; kc++)
        ldsm4(qa[kc][0], qa[kc][1], qa[kc][2], qa[kc][3],
              sb + QOFF_B + ((16 * rg + (l & 15)) * 40 + kc * 16 + (l >> 4) * 8) * 2);

    float oacc[16][4];
#pragma unroll
    for (int nt = 0; nt < 16; nt++)
#pragma unroll
        for (int i = 0; i < 4; i++) oacc[nt][i] = 0.f;
    float m0 = -INFINITY, m1 = -INFINITY, l0s = 0.f, l1s = 0.f;

    for (int t = 0; t < 64; t++) {
        CP_WAIT0();
        __syncthreads();            // K[t],V[t] resident; all prev reads done

        if (t + 1 < 64) {
            const u32 kd = sb + (((t + 1) & 1) ? K1_B : K0_B);
            const u32 vd = sb + (((t + 1) & 1) ? V1_B : V0_B);
            if (tid < 256) {
                int kr = tid >> 2, kc = tid & 3;
                CP16(kd + kr * 80 + kc * 16,
                     K4g + ((size_t)((b << 12) + (t + 1) * 64 + kr)) * 4 + kc);
            }
#pragma unroll
            for (int it = 0; it < 4; it++) {
                int e = tid + it * 512;
                int chn = e >> 3, cc = e & 7;
                CP16(vd + chn * 144 + cc * 16,
                     V4g + (((size_t)(b * C_ + chn)) << 9) + (t + 1) * 8 + cc);
            }
            CP_COMMIT();
        }

        // ---- S = Q K^T (R12-proven ldsm/mma pattern) ----
        const u32 kB = sb + ((t & 1) ? K1_B : K0_B);
        float s[8][4];
#pragma unroll
        for (int nt = 0; nt < 8; nt++)
#pragma unroll
            for (int i = 0; i < 4; i++) s[nt][i] = 0.f;
#pragma unroll
        for (int kc = 0; kc < 2; kc++) {
#pragma unroll
            for (int np = 0; np < 4; np++) {
                u32 k0, k1, k2, k3;
                ldsm4(k0, k1, k2, k3,
                      kB + ((16 * np + (l & 7) + ((l >> 4) & 1) * 8) * 40
                            + kc * 16 + ((l >> 3) & 1) * 8) * 2);
                mma16(s[2 * np],     qa[kc], k0, k1);
                mma16(s[2 * np + 1], qa[kc], k2, k3);
            }
        }

        // ---- online softmax (rows 16rg+rloc, +8); alpha in registers ----
        float rm0 = -INFINITY, rm1 = -INFINITY;
#pragma unroll
        for (int nt = 0; nt < 8; nt++) {
            rm0 = fmaxf(rm0, fmaxf(s[nt][0], s[nt][1]));
            rm1 = fmaxf(rm1, fmaxf(s[nt][2], s[nt][3]));
        }
        rm0 = fmaxf(rm0, __shfl_xor_sync(0xffffffffu, rm0, 1));
        rm0 = fmaxf(rm0, __shfl_xor_sync(0xffffffffu, rm0, 2));
        rm1 = fmaxf(rm1, __shfl_xor_sync(0xffffffffu, rm1, 1));
        rm1 = fmaxf(rm1, __shfl_xor_sync(0xffffffffu, rm1, 2));
        float mn0 = fmaxf(m0, rm0), mn1 = fmaxf(m1, rm1);
        float al0 = __expf(m0 - mn0), al1 = __expf(m1 - mn1);
        m0 = mn0; m1 = mn1;
        float ps0 = 0.f, ps1 = 0.f;
#pragma unroll
        for (int nt = 0; nt < 8; nt++) {
            s[nt][0] = __expf(s[nt][0] - mn0);
            s[nt][1] = __expf(s[nt][1] - mn0);
            s[nt][2] = __expf(s[nt][2] - mn1);
            s[nt][3] = __expf(s[nt][3] - mn1);
            ps0 += s[nt][0] + s[nt][1];
            ps1 += s[nt][2] + s[nt][3];
        }
        ps0 += __shfl_xor_sync(0xffffffffu, ps0, 1);
        ps0 += __shfl_xor_sync(0xffffffffu, ps0, 2);
        ps1 += __shfl_xor_sync(0xffffffffu, ps1, 1);
        ps1 += __shfl_xor_sync(0xffffffffu, ps1, 2);
        l0s = l0s * al0 + ps0;
        l1s = l1s * al1 + ps1;

        if (!__all_sync(0xffffffffu, (al0 == 1.f) && (al1 == 1.f))) {
#pragma unroll
            for (int nt = 0; nt < 16; nt++) {
                oacc[nt][0] *= al0; oacc[nt][1] *= al0;
                oacc[nt][2] *= al1; oacc[nt][3] *= al1;
            }
        }

        // ---- P store: per-warp PRIVATE region (rows w*16..w*16+16) ----
#pragma unroll
        for (int nt = 0; nt < 8; nt++) {
            *(u32*)(smem8 + P_B + ((w * 16 + rloc) * 72 + 8 * nt + 2 * kq) * 2) =
                bf2pack(s[nt][0], s[nt][1]);
            *(u32*)(smem8 + P_B + ((w * 16 + rloc + 8) * 72 + 8 * nt + 2 * kq) * 2) =
                bf2pack(s[nt][2], s[nt][3]);
        }
        __syncwarp();               // producer == consumer warp

        // ---- PV (R12-proven pattern; this warp's rows x its 128 chans) ----
        {
            u32 pa[4][4];
#pragma unroll
            for (int kc = 0; kc < 4; kc++)
                ldsm4(pa[kc][0], pa[kc][1], pa[kc][2], pa[kc][3],
                      sb + P_B + ((w * 16 + (l & 15)) * 72 + kc * 16 + (l >> 4) * 8) * 2);
            const u32 vB = sb + ((t & 1) ? V1_B : V0_B);
#pragma unroll
            for (int kc = 0; kc < 4; kc++) {
#pragma unroll
                for (int np = 0; np < 8; np++) {
                    u32 v0, v1, v2, v3;
                    ldsm4(v0, v1, v2, v3,
                          vB + ((cb + 16 * np + (l & 7) + ((l >> 4) & 1) * 8) * 72
                                + kc * 16 + ((l >> 3) & 1) * 8) * 2);
                    mma16(oacc[2 * np],     pa[kc], v0, v1);
                    mma16(oacc[2 * np + 1], pa[kc], v2, v3);
                }
            }
        }
        __syncwarp();               // P reads done before next-iter stores
    }

    // ---- epilogue: out = gamma*O/l + x; two 128-chan phases ----
    const float gm = gamma[0];
    const float g0 = gm / l0s, g1 = gm / l1s;
    const int row0 = 16 * rg + rloc, row1 = row0 + 8;
    float* ts = sm;                 // [cl][row] stride 132, 128 rows
#pragma unroll 1
    for (int ph = 0; ph < 2; ph++) {
        __syncthreads();
        if (chh == ph) {
#pragma unroll
            for (int np = 0; np < 8; np++) {
                int cl0 = 16 * np + 2 * kq;
                int cl1 = 16 * np + 8 + 2 * kq;
                ts[cl0 * 132 + row0]       = oacc[2 * np][0] * g0;
                ts[(cl0 + 1) * 132 + row0] = oacc[2 * np][1] * g0;
                ts[cl0 * 132 + row1]       = oacc[2 * np][2] * g1;
                ts[(cl0 + 1) * 132 + row1] = oacc[2 * np][3] * g1;
                ts[cl1 * 132 + row0]       = oacc[2 * np + 1][0] * g0;
                ts[(cl1 + 1) * 132 + row0] = oacc[2 * np + 1][1] * g0;
                ts[cl1 * 132 + row1]       = oacc[2 * np + 1][2] * g1;
                ts[(cl1 + 1) * 132 + row1] = oacc[2 * np + 1][3] * g1;
            }
        }
        __syncthreads();
#pragma unroll
        for (int it = 0; it < 8; it++) {
            int e = tid + it * 512;
            int c = e >> 5, r4 = e & 31;
            float4 o4 = *(const float4*)(ts + c * 132 + r4 * 4);
            size_t g4 = (size_t)(b * C_ + ph * 128 + c) * 1024 + (i0 >> 2) + r4;
            float4 x4 = ((const float4*)x)[g4];
            o4.x += x4.x; o4.y += x4.y; o4.z += x4.z; o4.w += x4.w;
            ((float4*)out)[g4] = o4;
        }
    }
}

// ---------------------------------------------------------------------------
extern "C" void kernel_launch(void* const* d_in, const int* in_sizes, int n_in,
                              void* d_out, int out_size)
{
    const float* x     = (const float*)d_in[0];
    const float* mask  = (const float*)d_in[1];
    const float* Wq    = (const float*)d_in[2];
    const float* bq    = (const float*)d_in[3];
    const float* Wk    = (const float*)d_in[4];
    const float* bk    = (const float*)d_in[5];
    const float* Wv    = (const float*)d_in[6];
    const float* bv    = (const float*)d_in[7];
    const float* gamma = (const float*)d_in[8];
    float* out = (float*)d_out;

    cudaFuncSetAttribute(attn_kernel,
                         cudaFuncAttributeMaxDynamicSharedMemorySize, A_SMEM_BYTES);

    dim3 pgrid(N_ / 64, 5, B_);
    proj_kernel<<<pgrid, 256>>>(x, mask, Wq, bq, Wk, bk, Wv, bv);

    dim3 agrid(N_ / 128, B_);
    attn_kernel<<<agrid, 512, A_SMEM_BYTES>>>(x, gamma, out);
}

// round 16
// speedup vs baseline: 3.3846x; 1.0423x over previous
#include <cuda_runtime.h>
#include <cuda_bf16.h>
#include <math.h>
#include <cstdint>

#define B_  4
#define C_  256
#define CQ_ 32
#define N_  4096
#define LOG2E 1.44269504088896f

typedef unsigned int u32;
typedef unsigned long long u64;

// bf16 scratch: Q/K [b][n][32] (Q pre-scaled by log2e); V channel-major [b][c][n]
__device__ __align__(256) __nv_bfloat16 g_Qh[(size_t)B_ * N_ * CQ_];
__device__ __align__(256) __nv_bfloat16 g_Kh[(size_t)B_ * N_ * CQ_];
__device__ __align__(256) __nv_bfloat16 g_Vh[(size_t)B_ * C_ * N_];

__device__ __forceinline__ u32 smem_u32(const void* p) {
    u32 a; asm("{ .reg .u64 t; cvta.to.shared.u64 t, %1; cvt.u32.u64 %0, t; }"
               : "=r"(a) : "l"(p)); return a;
}
__device__ __forceinline__ u32 bf2pack(float lo, float hi) {
    u32 r;
    asm("{ .reg .b16 a,b; cvt.rn.bf16.f32 a,%1; cvt.rn.bf16.f32 b,%2; mov.b32 %0,{a,b}; }"
        : "=r"(r) : "f"(lo), "f"(hi));
    return r;
}
__device__ __forceinline__ u64 pack2(float lo, float hi) {
    u64 r; asm("mov.b64 %0,{%1,%2};" : "=l"(r) : "f"(lo), "f"(hi)); return r;
}
__device__ __forceinline__ void unpack2(u64 v, float& lo, float& hi) {
    asm("mov.b64 {%0,%1},%2;" : "=f"(lo), "=f"(hi) : "l"(v));
}
__device__ __forceinline__ u64 fma2(u64 a, u64 b, u64 c) {
    u64 d; asm("fma.rn.f32x2 %0,%1,%2,%3;" : "=l"(d) : "l"(a), "l"(b), "l"(c)); return d;
}
__device__ __forceinline__ void mma16(float* d, const u32* a, u32 b0, u32 b1) {
    asm volatile("mma.sync.aligned.m16n8k16.row.col.f32.bf16.bf16.f32 "
        "{%0,%1,%2,%3},{%4,%5,%6,%7},{%8,%9},{%0,%1,%2,%3};"
        : "+f"(d[0]), "+f"(d[1]), "+f"(d[2]), "+f"(d[3])
        : "r"(a[0]), "r"(a[1]), "r"(a[2]), "r"(a[3]), "r"(b0), "r"(b1));
}
__device__ __forceinline__ void ldsm4(u32& r0, u32& r1, u32& r2, u32& r3, u32 addr) {
    asm volatile("ldmatrix.sync.aligned.m8n8.x4.shared.b16 {%0,%1,%2,%3},[%4];"
                 : "=r"(r0), "=r"(r1), "=r"(r2), "=r"(r3) : "r"(addr));
}
#define CP16(dst, src) \
    asm volatile("cp.async.cg.shared.global [%0],[%1],16;" :: "r"(dst), "l"(src) : "memory")
#define CP_COMMIT() asm volatile("cp.async.commit_group;" ::: "memory")
#define CP_WAIT0()  asm volatile("cp.async.wait_group 0;" ::: "memory")

// ---------------------------------------------------------------------------
// Kernel 1: QKV projection — R15 verbatim except q scaled by LOG2E.
// ---------------------------------------------------------------------------
__global__ void __launch_bounds__(256) proj_kernel(
    const float* __restrict__ x, const float* __restrict__ mask,
    const float* __restrict__ Wq, const float* __restrict__ bq,
    const float* __restrict__ Wk, const float* __restrict__ bk,
    const float* __restrict__ Wv, const float* __restrict__ bv)
{
    __shared__ float xs[64 * 64];
    __shared__ float wsT[64 * 65];

    const int tid = threadIdx.x;
    const int tx = tid & 15, ty = tid >> 4;
    const int pix0 = blockIdx.x * 64;
    const int g = blockIdx.y;
    const int b = blockIdx.z;

    u64 acc2[2][4];
#pragma unroll
    for (int i = 0; i < 2; i++)
#pragma unroll
        for (int j = 0; j < 4; j++) acc2[i][j] = 0ULL;

    for (int ch = 0; ch < 4; ch++) {
        const int c0 = ch * 64;
        __syncthreads();
        {
            const float4* X4 = (const float4*)x;
            float4* xs4 = (float4*)xs;
#pragma unroll
            for (int it = 0; it < 4; it++) {
                int e4 = tid + it * 256;
                int cc = e4 >> 4, p4 = e4 & 15;
                xs4[cc * 16 + p4] =
                    X4[(size_t)(b * C_ + c0 + cc) * (N_ / 4) + (pix0 >> 2) + p4];
            }
        }
        {
#pragma unroll
            for (int it = 0; it < 4; it++) {
                int e4 = tid + it * 256;
                int o = e4 >> 4, c4 = e4 & 15;
                const float* wrow;
                if (g == 0) wrow = (o < 32) ? (Wq + o * C_) : (Wk + (o - 32) * C_);
                else        wrow = Wv + ((g - 1) * 64 + o) * C_;
                float4 w4 = *(const float4*)(wrow + c0 + c4 * 4);
                wsT[(c4 * 4 + 0) * 65 + o] = w4.x;
                wsT[(c4 * 4 + 1) * 65 + o] = w4.y;
                wsT[(c4 * 4 + 2) * 65 + o] = w4.z;
                wsT[(c4 * 4 + 3) * 65 + o] = w4.w;
            }
        }
        __syncthreads();
        const u64* xs2 = (const u64*)xs;
#pragma unroll 8
        for (int cc = 0; cc < 64; cc++) {
            u64 xr0 = xs2[cc * 32 + ty * 2];
            u64 xr1 = xs2[cc * 32 + ty * 2 + 1];
#pragma unroll
            for (int rr = 0; rr < 4; rr++) {
                float wv = wsT[cc * 65 + tx + 16 * rr];
                u64 w2 = pack2(wv, wv);
                acc2[0][rr] = fma2(xr0, w2, acc2[0][rr]);
                acc2[1][rr] = fma2(xr1, w2, acc2[1][rr]);
            }
        }
    }

    float acc[4][4];
#pragma unroll
    for (int p2 = 0; p2 < 2; p2++)
#pragma unroll
        for (int rr = 0; rr < 4; rr++)
            unpack2(acc2[p2][rr], acc[2 * p2][rr], acc[2 * p2 + 1][rr]);

    if (g == 0) {
#pragma unroll
        for (int pp = 0; pp < 4; pp++) {
            int p = ty * 4 + pp;
            float mv = mask[(b << 12) + pix0 + p];
#pragma unroll
            for (int rr = 0; rr < 4; rr++) {
                int o = tx + 16 * rr;
                if (o < 32) {
                    g_Qh[((size_t)(b << 12) + pix0 + p) * CQ_ + o] =
                        __float2bfloat16_rn((acc[pp][rr] + bq[o]) * mv * LOG2E);
                } else {
                    g_Kh[((size_t)(b << 12) + pix0 + p) * CQ_ + (o - 32)] =
                        __float2bfloat16_rn((acc[pp][rr] + bk[o - 32]) * mv);
                }
            }
        }
    } else {
#pragma unroll
        for (int pp = 0; pp < 4; pp++) {
            int p = ty * 4 + pp;
#pragma unroll
            for (int rr = 0; rr < 4; rr++) {
                int vo = (g - 1) * 64 + tx + 16 * rr;
                g_Vh[(((size_t)(b * C_ + vo)) << 12) + pix0 + p] =
                    __float2bfloat16_rn(acc[pp][rr] + bv[vo]);
            }
        }
    }
}

// ---------------------------------------------------------------------------
// Kernel 2: pipelined flash attention. 128 q/CTA, grid (32,B), 512 threads.
// Per-warp loop: QK(t) -> [rescale; PV(t-1)] -> softmax(t) -> Pstore(t).
// PV tensor work overlaps softmax latency. V triple-buffered (PV reads t-1
// while prefetching t+1); P double-buffered per warp. All ldsm/mma blocks
// are the R12/R15-proven patterns; only buffer indices changed.
// smem: Q[128x80B] | K 2x[64x80B] | V 3x[256x144B] | P 2x[256rows x 144B]
// ---------------------------------------------------------------------------
#define QOFF_B  0
#define K0_B    10240
#define V0_B    20480
#define VBUF_B  36864
#define P0_B    131072
#define PBUF_B  36864
#define A_SMEM_BYTES 204800

__global__ void __launch_bounds__(512, 1)
attn_kernel(const float* __restrict__ x, const float* __restrict__ gamma,
            float* __restrict__ out)
{
    extern __shared__ float sm[];
    char* smem8 = (char*)sm;
    const u32 sb = smem_u32(sm);

    const int tid = threadIdx.x;
    const int w = tid >> 5, l = tid & 31;
    const int kq = l & 3, rloc = l >> 2;
    const int rg = w & 7;                  // row group: rows [16rg, 16rg+16)
    const int chh = w >> 3;                // channel half
    const int cb = chh * 128;              // channel base
    const int b = blockIdx.y;
    const int i0 = blockIdx.x * 128;

    const uint4* Q4g = (const uint4*)g_Qh;
    const uint4* K4g = (const uint4*)g_Kh;
    const uint4* V4g = (const uint4*)g_Vh;

    // ---- prologue: stage Q; cp.async K(0) + V(0) into buf 0 ----
    {
        int row = tid >> 2, c = tid & 3;
        *(uint4*)(smem8 + QOFF_B + row * 80 + c * 16) =
            Q4g[((size_t)((b << 12) + i0 + row)) * 4 + c];
        if (tid < 256) {
            int kr = tid >> 2, kc = tid & 3;
            CP16(sb + K0_B + kr * 80 + kc * 16,
                 K4g + ((size_t)(b << 12) + kr) * 4 + kc);
        }
#pragma unroll
        for (int it = 0; it < 4; it++) {
            int e = tid + it * 512;
            int chn = e >> 3, cc = e & 7;
            CP16(sb + V0_B + chn * 144 + cc * 16,
                 V4g + (((size_t)(b * C_ + chn)) << 9) + cc);
        }
        CP_COMMIT();
    }
    __syncthreads();

    // Q A-frags (R12-proven pattern, stride 40h)
    u32 qa[2][4];
#pragma unroll
    for (int kc = 0; kc < 2; kc++)
        ldsm4(qa[kc][0], qa[kc][1], qa[kc][2], qa[kc][3],
              sb + QOFF_B + ((16 * rg + (l & 15)) * 40 + kc * 16 + (l >> 4) * 8) * 2);

    float oacc[16][4];
#pragma unroll
    for (int nt = 0; nt < 16; nt++)
#pragma unroll
        for (int i = 0; i < 4; i++) oacc[nt][i] = 0.f;
    float m0 = -INFINITY, m1 = -INFINITY, l0s = 0.f, l1s = 0.f;
    float al0p = 1.f, al1p = 1.f;          // alpha from previous tile

    for (int t = 0; t < 64; t++) {
        const int vcur = t % 3;
        CP_WAIT0();
        __syncthreads();            // K(t),V(t) resident; all PV(t-2) reads done

        if (t + 1 < 64) {
            const u32 kd = sb + K0_B + ((t + 1) & 1) * 5120;
            const u32 vd = sb + V0_B + ((t + 1) % 3) * VBUF_B;
            if (tid < 256) {
                int kr = tid >> 2, kc = tid & 3;
                CP16(kd + kr * 80 + kc * 16,
                     K4g + ((size_t)((b << 12) + (t + 1) * 64 + kr)) * 4 + kc);
            }
#pragma unroll
            for (int it = 0; it < 4; it++) {
                int e = tid + it * 512;
                int chn = e >> 3, cc = e & 7;
                CP16(vd + chn * 144 + cc * 16,
                     V4g + (((size_t)(b * C_ + chn)) << 9) + (t + 1) * 8 + cc);
            }
            CP_COMMIT();
        }

        // ---- S = Q K^T (R12-proven pattern); issues into tensor pipe ----
        const u32 kB = sb + K0_B + (t & 1) * 5120;
        float s[8][4];
#pragma unroll
        for (int nt = 0; nt < 8; nt++)
#pragma unroll
            for (int i = 0; i < 4; i++) s[nt][i] = 0.f;
#pragma unroll
        for (int kc = 0; kc < 2; kc++) {
#pragma unroll
            for (int np = 0; np < 4; np++) {
                u32 k0, k1, k2, k3;
                ldsm4(k0, k1, k2, k3,
                      kB + ((16 * np + (l & 7) + ((l >> 4) & 1) * 8) * 40
                            + kc * 16 + ((l >> 3) & 1) * 8) * 2);
                mma16(s[2 * np],     qa[kc], k0, k1);
                mma16(s[2 * np + 1], qa[kc], k2, k3);
            }
        }

        // ---- PV(t-1): issued before softmax so tensor work overlaps it ----
        if (t > 0) {
            if (!__all_sync(0xffffffffu, (al0p == 1.f) && (al1p == 1.f))) {
#pragma unroll
                for (int nt = 0; nt < 16; nt++) {
                    oacc[nt][0] *= al0p; oacc[nt][1] *= al0p;
                    oacc[nt][2] *= al1p; oacc[nt][3] *= al1p;
                }
            }
            const u32 pB = sb + P0_B + ((t - 1) & 1) * PBUF_B;
            u32 pa[4][4];
#pragma unroll
            for (int kc = 0; kc < 4; kc++)
                ldsm4(pa[kc][0], pa[kc][1], pa[kc][2], pa[kc][3],
                      pB + ((w * 16 + (l & 15)) * 72 + kc * 16 + (l >> 4) * 8) * 2);
            const u32 vB = sb + V0_B + ((t + 2) % 3) * VBUF_B;   // (t-1)%3
#pragma unroll
            for (int kc = 0; kc < 4; kc++) {
#pragma unroll
                for (int np = 0; np < 8; np++) {
                    u32 v0, v1, v2, v3;
                    ldsm4(v0, v1, v2, v3,
                          vB + ((cb + 16 * np + (l & 7) + ((l >> 4) & 1) * 8) * 72
                                + kc * 16 + ((l >> 3) & 1) * 8) * 2);
                    mma16(oacc[2 * np],     pa[kc], v0, v1);
                    mma16(oacc[2 * np + 1], pa[kc], v2, v3);
                }
            }
        }

        // ---- softmax(t) on base-2 logits; runs while PV mmas drain ----
        float rm0 = -INFINITY, rm1 = -INFINITY;
#pragma unroll
        for (int nt = 0; nt < 8; nt++) {
            rm0 = fmaxf(rm0, fmaxf(s[nt][0], s[nt][1]));
            rm1 = fmaxf(rm1, fmaxf(s[nt][2], s[nt][3]));
        }
        rm0 = fmaxf(rm0, __shfl_xor_sync(0xffffffffu, rm0, 1));
        rm0 = fmaxf(rm0, __shfl_xor_sync(0xffffffffu, rm0, 2));
        rm1 = fmaxf(rm1, __shfl_xor_sync(0xffffffffu, rm1, 1));
        rm1 = fmaxf(rm1, __shfl_xor_sync(0xffffffffu, rm1, 2));
        float mn0 = fmaxf(m0, rm0), mn1 = fmaxf(m1, rm1);
        float al0 = exp2f(m0 - mn0), al1 = exp2f(m1 - mn1);
        m0 = mn0; m1 = mn1;
        float ps0 = 0.f, ps1 = 0.f;
#pragma unroll
        for (int nt = 0; nt < 8; nt++) {
            s[nt][0] = exp2f(s[nt][0] - mn0);
            s[nt][1] = exp2f(s[nt][1] - mn0);
            s[nt][2] = exp2f(s[nt][2] - mn1);
            s[nt][3] = exp2f(s[nt][3] - mn1);
            ps0 += s[nt][0] + s[nt][1];
            ps1 += s[nt][2] + s[nt][3];
        }
        ps0 += __shfl_xor_sync(0xffffffffu, ps0, 1);
        ps0 += __shfl_xor_sync(0xffffffffu, ps0, 2);
        ps1 += __shfl_xor_sync(0xffffffffu, ps1, 1);
        ps1 += __shfl_xor_sync(0xffffffffu, ps1, 2);
        l0s = l0s * al0 + ps0;
        l1s = l1s * al1 + ps1;
        al0p = al0; al1p = al1;

        // ---- P store (per-warp private, D-layout; buffer t&1) ----
        {
            char* pS = smem8 + P0_B + (t & 1) * PBUF_B;
#pragma unroll
            for (int nt = 0; nt < 8; nt++) {
                *(u32*)(pS + ((w * 16 + rloc) * 72 + 8 * nt + 2 * kq) * 2) =
                    bf2pack(s[nt][0], s[nt][1]);
                *(u32*)(pS + ((w * 16 + rloc + 8) * 72 + 8 * nt + 2 * kq) * 2) =
                    bf2pack(s[nt][2], s[nt][3]);
            }
        }
        __syncwarp();
    }

    // ---- final PV(63) ----
    {
        if (!__all_sync(0xffffffffu, (al0p == 1.f) && (al1p == 1.f))) {
#pragma unroll
            for (int nt = 0; nt < 16; nt++) {
                oacc[nt][0] *= al0p; oacc[nt][1] *= al0p;
                oacc[nt][2] *= al1p; oacc[nt][3] *= al1p;
            }
        }
        const u32 pB = sb + P0_B + (63 & 1) * PBUF_B;
        u32 pa[4][4];
#pragma unroll
        for (int kc = 0; kc < 4; kc++)
            ldsm4(pa[kc][0], pa[kc][1], pa[kc][2], pa[kc][3],
                  pB + ((w * 16 + (l & 15)) * 72 + kc * 16 + (l >> 4) * 8) * 2);
        const u32 vB = sb + V0_B + (63 % 3) * VBUF_B;
#pragma unroll
        for (int kc = 0; kc < 4; kc++) {
#pragma unroll
            for (int np = 0; np < 8; np++) {
                u32 v0, v1, v2, v3;
                ldsm4(v0, v1, v2, v3,
                      vB + ((cb + 16 * np + (l & 7) + ((l >> 4) & 1) * 8) * 72
                            + kc * 16 + ((l >> 3) & 1) * 8) * 2);
                mma16(oacc[2 * np],     pa[kc], v0, v1);
                mma16(oacc[2 * np + 1], pa[kc], v2, v3);
            }
        }
    }

    // ---- epilogue: out = gamma*O/l + x; two 128-chan phases ----
    const float gm = gamma[0];
    const float g0 = gm / l0s, g1 = gm / l1s;
    const int row0 = 16 * rg + rloc, row1 = row0 + 8;
    float* ts = sm;                 // [cl][row] stride 132
#pragma unroll 1
    for (int ph = 0; ph < 2; ph++) {
        __syncthreads();
        if (chh == ph) {
#pragma unroll
            for (int np = 0; np < 8; np++) {
                int cl0 = 16 * np + 2 * kq;
                int cl1 = 16 * np + 8 + 2 * kq;
                ts[cl0 * 132 + row0]       = oacc[2 * np][0] * g0;
                ts[(cl0 + 1) * 132 + row0] = oacc[2 * np][1] * g0;
                ts[cl0 * 132 + row1]       = oacc[2 * np][2] * g1;
                ts[(cl0 + 1) * 132 + row1] = oacc[2 * np][3] * g1;
                ts[cl1 * 132 + row0]       = oacc[2 * np + 1][0] * g0;
                ts[(cl1 + 1) * 132 + row0] = oacc[2 * np + 1][1] * g0;
                ts[cl1 * 132 + row1]       = oacc[2 * np + 1][2] * g1;
                ts[(cl1 + 1) * 132 + row1] = oacc[2 * np + 1][3] * g1;
            }
        }
        __syncthreads();
#pragma unroll
        for (int it = 0; it < 8; it++) {
            int e = tid + it * 512;
            int c = e >> 5, r4 = e & 31;
            float4 o4 = *(const float4*)(ts + c * 132 + r4 * 4);
            size_t g4 = (size_t)(b * C_ + ph * 128 + c) * 1024 + (i0 >> 2) + r4;
            float4 x4 = ((const float4*)x)[g4];
            o4.x += x4.x; o4.y += x4.y; o4.z += x4.z; o4.w += x4.w;
            ((float4*)out)[g4] = o4;
        }
    }
}

// ---------------------------------------------------------------------------
extern "C" void kernel_launch(void* const* d_in, const int* in_sizes, int n_in,
                              void* d_out, int out_size)
{
    const float* x     = (const float*)d_in[0];
    const float* mask  = (const float*)d_in[1];
    const float* Wq    = (const float*)d_in[2];
    const float* bq    = (const float*)d_in[3];
    const float* Wk    = (const float*)d_in[4];
    const float* bk    = (const float*)d_in[5];
    const float* Wv    = (const float*)d_in[6];
    const float* bv    = (const float*)d_in[7];
    const float* gamma = (const float*)d_in[8];
    float* out = (float*)d_out;

    cudaFuncSetAttribute(attn_kernel,
                         cudaFuncAttributeMaxDynamicSharedMemorySize, A_SMEM_BYTES);

    dim3 pgrid(N_ / 64, 5, B_);
    proj_kernel<<<pgrid, 256>>>(x, mask, Wq, bq, Wk, bk, Wv, bv);

    dim3 agrid(N_ / 128, B_);
    attn_kernel<<<agrid, 512, A_SMEM_BYTES>>>(x, gamma, out);
}

// round 17
// speedup vs baseline: 3.4336x; 1.0145x over previous
#include <cuda_runtime.h>
#include <cuda_bf16.h>
#include <math.h>
#include <cstdint>

#define B_  4
#define C_  256
#define CQ_ 32
#define N_  4096
#define LOG2E 1.44269504088896f

typedef unsigned int u32;
typedef unsigned long long u64;

// bf16 scratch:
//  Q  [b][n][32] (pre-scaled by log2e)            — row-major, 64B rows
//  Kt [b][t][64 rows x 128B swizzled tile image]  — 8KB per (b,t)
//  Vt [b][t][256 chans x 128B swizzled tile image]— 32KB per (b,t)
// swizzle: 16B-chunk index c stored at position (c ^ (row&7)) within the row.
__device__ __align__(256) __nv_bfloat16 g_Qh[(size_t)B_ * N_ * CQ_];
__device__ __align__(256) __nv_bfloat16 g_Kt[(size_t)B_ * 64 * 4096];
__device__ __align__(256) __nv_bfloat16 g_Vt[(size_t)B_ * 64 * 16384];

__device__ __forceinline__ u32 smem_u32(const void* p) {
    u32 a; asm("{ .reg .u64 t; cvta.to.shared.u64 t, %1; cvt.u32.u64 %0, t; }"
               : "=r"(a) : "l"(p)); return a;
}
__device__ __forceinline__ u32 bf2pack(float lo, float hi) {
    u32 r;
    asm("{ .reg .b16 a,b; cvt.rn.bf16.f32 a,%1; cvt.rn.bf16.f32 b,%2; mov.b32 %0,{a,b}; }"
        : "=r"(r) : "f"(lo), "f"(hi));
    return r;
}
__device__ __forceinline__ u64 pack2(float lo, float hi) {
    u64 r; asm("mov.b64 %0,{%1,%2};" : "=l"(r) : "f"(lo), "f"(hi)); return r;
}
__device__ __forceinline__ void unpack2(u64 v, float& lo, float& hi) {
    asm("mov.b64 {%0,%1},%2;" : "=f"(lo), "=f"(hi) : "l"(v));
}
__device__ __forceinline__ u64 fma2(u64 a, u64 b, u64 c) {
    u64 d; asm("fma.rn.f32x2 %0,%1,%2,%3;" : "=l"(d) : "l"(a), "l"(b), "l"(c)); return d;
}
__device__ __forceinline__ void mma16(float* d, const u32* a, u32 b0, u32 b1) {
    asm volatile("mma.sync.aligned.m16n8k16.row.col.f32.bf16.bf16.f32 "
        "{%0,%1,%2,%3},{%4,%5,%6,%7},{%8,%9},{%0,%1,%2,%3};"
        : "+f"(d[0]), "+f"(d[1]), "+f"(d[2]), "+f"(d[3])
        : "r"(a[0]), "r"(a[1]), "r"(a[2]), "r"(a[3]), "r"(b0), "r"(b1));
}
__device__ __forceinline__ void ldsm4(u32& r0, u32& r1, u32& r2, u32& r3, u32 addr) {
    asm volatile("ldmatrix.sync.aligned.m8n8.x4.shared.b16 {%0,%1,%2,%3},[%4];"
                 : "=r"(r0), "=r"(r1), "=r"(r2), "=r"(r3) : "r"(addr));
}

#define MBAR_INIT(mb, n) \
    asm volatile("mbarrier.init.shared.b64 [%0], %1;" :: "r"((u32)(mb)), "r"((u32)(n)) : "memory")
#define MBAR_EXPECT_TX(mb, bytes) \
    asm volatile("mbarrier.arrive.expect_tx.shared.b64 _, [%0], %1;" \
                 :: "r"((u32)(mb)), "r"((u32)(bytes)) : "memory")
#define BULK_CP(dst, src, bytes, mb) \
    asm volatile("cp.async.bulk.shared::cluster.global.mbarrier::complete_tx::bytes " \
                 "[%0], [%1], %2, [%3];" \
                 :: "r"((u32)(dst)), "l"(src), "r"((u32)(bytes)), "r"((u32)(mb)) : "memory")
#define MBAR_WAIT(mb, ph) do {                                                       \
    u32 _mb = (u32)(mb), _ph = (u32)(ph), _done;                                     \
    asm volatile("{ .reg .pred p; mbarrier.try_wait.parity.acquire.cta.shared::cta.b64 p,[%1],%2;" \
                 " selp.b32 %0,1,0,p; }" : "=r"(_done) : "r"(_mb), "r"(_ph) : "memory"); \
    if (!_done) {                                                                    \
        asm volatile("{ .reg .pred P1; WL_%=:"                                       \
            " mbarrier.try_wait.parity.acquire.cta.shared::cta.b64 P1,[%0],%1,0x989680;" \
            " @P1 bra.uni WD_%=; bra.uni WL_%=; WD_%=: }"                            \
            :: "r"(_mb), "r"(_ph) : "memory");                                       \
    }                                                                                \
} while (0)

// ---------------------------------------------------------------------------
// Kernel 1: QKV projection — proven GEMM core; K/V stored to pre-swizzled
// tile-major images, Q unchanged ([b][n][32], *log2e).
// ---------------------------------------------------------------------------
__global__ void __launch_bounds__(256) proj_kernel(
    const float* __restrict__ x, const float* __restrict__ mask,
    const float* __restrict__ Wq, const float* __restrict__ bq,
    const float* __restrict__ Wk, const float* __restrict__ bk,
    const float* __restrict__ Wv, const float* __restrict__ bv)
{
    __shared__ float xs[64 * 64];
    __shared__ float wsT[64 * 65];

    const int tid = threadIdx.x;
    const int tx = tid & 15, ty = tid >> 4;
    const int pix0 = blockIdx.x * 64;
    const int g = blockIdx.y;
    const int b = blockIdx.z;

    u64 acc2[2][4];
#pragma unroll
    for (int i = 0; i < 2; i++)
#pragma unroll
        for (int j = 0; j < 4; j++) acc2[i][j] = 0ULL;

    for (int ch = 0; ch < 4; ch++) {
        const int c0 = ch * 64;
        __syncthreads();
        {
            const float4* X4 = (const float4*)x;
            float4* xs4 = (float4*)xs;
#pragma unroll
            for (int it = 0; it < 4; it++) {
                int e4 = tid + it * 256;
                int cc = e4 >> 4, p4 = e4 & 15;
                xs4[cc * 16 + p4] =
                    X4[(size_t)(b * C_ + c0 + cc) * (N_ / 4) + (pix0 >> 2) + p4];
            }
        }
        {
#pragma unroll
            for (int it = 0; it < 4; it++) {
                int e4 = tid + it * 256;
                int o = e4 >> 4, c4 = e4 & 15;
                const float* wrow;
                if (g == 0) wrow = (o < 32) ? (Wq + o * C_) : (Wk + (o - 32) * C_);
                else        wrow = Wv + ((g - 1) * 64 + o) * C_;
                float4 w4 = *(const float4*)(wrow + c0 + c4 * 4);
                wsT[(c4 * 4 + 0) * 65 + o] = w4.x;
                wsT[(c4 * 4 + 1) * 65 + o] = w4.y;
                wsT[(c4 * 4 + 2) * 65 + o] = w4.z;
                wsT[(c4 * 4 + 3) * 65 + o] = w4.w;
            }
        }
        __syncthreads();
        const u64* xs2 = (const u64*)xs;
#pragma unroll 8
        for (int cc = 0; cc < 64; cc++) {
            u64 xr0 = xs2[cc * 32 + ty * 2];
            u64 xr1 = xs2[cc * 32 + ty * 2 + 1];
#pragma unroll
            for (int rr = 0; rr < 4; rr++) {
                float wv = wsT[cc * 65 + tx + 16 * rr];
                u64 w2 = pack2(wv, wv);
                acc2[0][rr] = fma2(xr0, w2, acc2[0][rr]);
                acc2[1][rr] = fma2(xr1, w2, acc2[1][rr]);
            }
        }
    }

    float acc[4][4];
#pragma unroll
    for (int p2 = 0; p2 < 2; p2++)
#pragma unroll
        for (int rr = 0; rr < 4; rr++)
            unpack2(acc2[p2][rr], acc[2 * p2][rr], acc[2 * p2 + 1][rr]);

    if (g == 0) {
#pragma unroll
        for (int pp = 0; pp < 4; pp++) {
            int p = ty * 4 + pp;
            int n = pix0 + p;
            float mv = mask[(b << 12) + n];
            int t = n >> 6, row = n & 63;
#pragma unroll
            for (int rr = 0; rr < 4; rr++) {
                int o = tx + 16 * rr;
                if (o < 32) {
                    g_Qh[((size_t)(b << 12) + n) * CQ_ + o] =
                        __float2bfloat16_rn((acc[pp][rr] + bq[o]) * mv * LOG2E);
                } else {
                    int k = o - 32;
                    int c = k >> 3, w8 = k & 7;
                    g_Kt[((size_t)(b * 64 + t)) * 4096 + row * 64
                         + ((c ^ (row & 7)) * 8) + w8] =
                        __float2bfloat16_rn((acc[pp][rr] + bk[k]) * mv);
                }
            }
        }
    } else {
#pragma unroll
        for (int pp = 0; pp < 4; pp++) {
            int p = ty * 4 + pp;
            int n = pix0 + p;
            int t = n >> 6, kt = n & 63;
            int c = kt >> 3, w8 = kt & 7;
#pragma unroll
            for (int rr = 0; rr < 4; rr++) {
                int vo = (g - 1) * 64 + tx + 16 * rr;
                g_Vt[((size_t)(b * 64 + t)) * 16384 + vo * 64
                     + (((c ^ (vo & 7)) * 8)) + w8] =
                    __float2bfloat16_rn(acc[pp][rr] + bv[vo]);
            }
        }
    }
}

// ---------------------------------------------------------------------------
// Kernel 2: pipelined flash attention with bulk-copy staging.
// 128 q/CTA, grid (32,B), 512 threads. Per-warp loop:
//   QK(t) -> [rescale; PV(t-1)] -> softmax(t) -> Pstore(t).
// K+V staged per tile by 2 cp.async.bulk (one thread) + mbarrier, 3 stages.
// smem: Q[128x80B] | 3 x (K 8KB + V 32KB) | P 2x36KB | 3 mbars
// ---------------------------------------------------------------------------
#define QOFF_B  0
#define ST_B    10240
#define ST_STR  40960
#define P0_B    133120
#define PBUF_B  36864
#define MBAR_B  206848
#define A_SMEM_BYTES 207104

__global__ void __launch_bounds__(512, 1)
attn_kernel(const float* __restrict__ x, const float* __restrict__ gamma,
            float* __restrict__ out)
{
    extern __shared__ float sm[];
    char* smem8 = (char*)sm;
    const u32 sb = smem_u32(sm);

    const int tid = threadIdx.x;
    const int w = tid >> 5, l = tid & 31;
    const int kq = l & 3, rloc = l >> 2;
    const int rg = w & 7;                  // row group: rows [16rg, 16rg+16)
    const int chh = w >> 3;                // channel half
    const int cb = chh * 128;              // channel base
    const int b = blockIdx.y;
    const int i0 = blockIdx.x * 128;

    const uint4* Q4g = (const uint4*)g_Qh;
    const char* Ktb = (const char*)(g_Kt + ((size_t)(b * 64)) * 4096);
    const char* Vtb = (const char*)(g_Vt + ((size_t)(b * 64)) * 16384);

    // ---- prologue: stage Q; init mbars; bulk stage 0 ----
    {
        int row = tid >> 2, c = tid & 3;
        *(uint4*)(smem8 + QOFF_B + row * 80 + c * 16) =
            Q4g[((size_t)((b << 12) + i0 + row)) * 4 + c];
    }
    if (tid == 0) {
#pragma unroll
        for (int s = 0; s < 3; s++) MBAR_INIT(sb + MBAR_B + s * 8, 1);
    }
    __syncthreads();
    if (tid == 0) {
        u32 mb = sb + MBAR_B;
        MBAR_EXPECT_TX(mb, 40960);
        BULK_CP(sb + ST_B, Ktb, 8192, mb);
        BULK_CP(sb + ST_B + 8192, Vtb, 32768, mb);
    }

    // Q A-frags (proven pattern, stride 40h)
    u32 qa[2][4];
#pragma unroll
    for (int kc = 0; kc < 2; kc++)
        ldsm4(qa[kc][0], qa[kc][1], qa[kc][2], qa[kc][3],
              sb + QOFF_B + ((16 * rg + (l & 15)) * 40 + kc * 16 + (l >> 4) * 8) * 2);

    float oacc[16][4];
#pragma unroll
    for (int nt = 0; nt < 16; nt++)
#pragma unroll
        for (int i = 0; i < 4; i++) oacc[nt][i] = 0.f;
    float m0 = -INFINITY, m1 = -INFINITY, l0s = 0.f, l1s = 0.f;
    float al0p = 1.f, al1p = 1.f;

    for (int t = 0; t < 64; t++) {
        __syncthreads();            // all reads of buffer (t+1)%3 (tile t-2) done

        if ((t + 1 < 64) && (tid == 0)) {
            int s = (t + 1) % 3;
            u32 mb = sb + MBAR_B + s * 8;
            MBAR_EXPECT_TX(mb, 40960);
            BULK_CP(sb + ST_B + s * ST_STR, Ktb + (size_t)(t + 1) * 8192, 8192, mb);
            BULK_CP(sb + ST_B + s * ST_STR + 8192,
                    Vtb + (size_t)(t + 1) * 32768, 32768, mb);
        }

        MBAR_WAIT(sb + MBAR_B + (t % 3) * 8, (t / 3) & 1);

        const u32 kB = sb + ST_B + (t % 3) * ST_STR;
        const u32 vB = kB + 8192;

        // ---- S = Q K^T (swizzled-image addressing) ----
        float s[8][4];
#pragma unroll
        for (int nt = 0; nt < 8; nt++)
#pragma unroll
            for (int i = 0; i < 4; i++) s[nt][i] = 0.f;
#pragma unroll
        for (int kc = 0; kc < 2; kc++) {
#pragma unroll
            for (int np = 0; np < 4; np++) {
                int krow = 16 * np + (l & 7) + ((l >> 4) & 1) * 8;
                int kchk = kc * 2 + ((l >> 3) & 1);
                u32 k0, k1, k2, k3;
                ldsm4(k0, k1, k2, k3,
                      kB + krow * 128 + ((kchk ^ (krow & 7)) * 16));
                mma16(s[2 * np],     qa[kc], k0, k1);
                mma16(s[2 * np + 1], qa[kc], k2, k3);
            }
        }

        // ---- PV(t-1): overlaps softmax(t) ----
        if (t > 0) {
            if (!__all_sync(0xffffffffu, (al0p == 1.f) && (al1p == 1.f))) {
#pragma unroll
                for (int nt = 0; nt < 16; nt++) {
                    oacc[nt][0] *= al0p; oacc[nt][1] *= al0p;
                    oacc[nt][2] *= al1p; oacc[nt][3] *= al1p;
                }
            }
            const u32 pB = sb + P0_B + ((t - 1) & 1) * PBUF_B;
            u32 pa[4][4];
#pragma unroll
            for (int kc = 0; kc < 4; kc++)
                ldsm4(pa[kc][0], pa[kc][1], pa[kc][2], pa[kc][3],
                      pB + ((w * 16 + (l & 15)) * 72 + kc * 16 + (l >> 4) * 8) * 2);
            const u32 vBp = sb + ST_B + ((t + 2) % 3) * ST_STR + 8192;  // (t-1)%3
#pragma unroll
            for (int kc = 0; kc < 4; kc++) {
#pragma unroll
                for (int np = 0; np < 8; np++) {
                    int chan = cb + 16 * np + (l & 7) + ((l >> 4) & 1) * 8;
                    int vchk = kc * 2 + ((l >> 3) & 1);
                    u32 v0, v1, v2, v3;
                    ldsm4(v0, v1, v2, v3,
                          vBp + chan * 128 + ((vchk ^ (chan & 7)) * 16));
                    mma16(oacc[2 * np],     pa[kc], v0, v1);
                    mma16(oacc[2 * np + 1], pa[kc], v2, v3);
                }
            }
        }

        // ---- softmax(t), base-2 ----
        float rm0 = -INFINITY, rm1 = -INFINITY;
#pragma unroll
        for (int nt = 0; nt < 8; nt++) {
            rm0 = fmaxf(rm0, fmaxf(s[nt][0], s[nt][1]));
            rm1 = fmaxf(rm1, fmaxf(s[nt][2], s[nt][3]));
        }
        rm0 = fmaxf(rm0, __shfl_xor_sync(0xffffffffu, rm0, 1));
        rm0 = fmaxf(rm0, __shfl_xor_sync(0xffffffffu, rm0, 2));
        rm1 = fmaxf(rm1, __shfl_xor_sync(0xffffffffu, rm1, 1));
        rm1 = fmaxf(rm1, __shfl_xor_sync(0xffffffffu, rm1, 2));
        float mn0 = fmaxf(m0, rm0), mn1 = fmaxf(m1, rm1);
        float al0 = exp2f(m0 - mn0), al1 = exp2f(m1 - mn1);
        m0 = mn0; m1 = mn1;
        float ps0 = 0.f, ps1 = 0.f;
#pragma unroll
        for (int nt = 0; nt < 8; nt++) {
            s[nt][0] = exp2f(s[nt][0] - mn0);
            s[nt][1] = exp2f(s[nt][1] - mn0);
            s[nt][2] = exp2f(s[nt][2] - mn1);
            s[nt][3] = exp2f(s[nt][3] - mn1);
            ps0 += s[nt][0] + s[nt][1];
            ps1 += s[nt][2] + s[nt][3];
        }
        ps0 += __shfl_xor_sync(0xffffffffu, ps0, 1);
        ps0 += __shfl_xor_sync(0xffffffffu, ps0, 2);
        ps1 += __shfl_xor_sync(0xffffffffu, ps1, 1);
        ps1 += __shfl_xor_sync(0xffffffffu, ps1, 2);
        l0s = l0s * al0 + ps0;
        l1s = l1s * al1 + ps1;
        al0p = al0; al1p = al1;

        // ---- P store (per-warp private, D-layout; buffer t&1) ----
        {
            char* pS = smem8 + P0_B + (t & 1) * PBUF_B;
#pragma unroll
            for (int nt = 0; nt < 8; nt++) {
                *(u32*)(pS + ((w * 16 + rloc) * 72 + 8 * nt + 2 * kq) * 2) =
                    bf2pack(s[nt][0], s[nt][1]);
                *(u32*)(pS + ((w * 16 + rloc + 8) * 72 + 8 * nt + 2 * kq) * 2) =
                    bf2pack(s[nt][2], s[nt][3]);
            }
        }
        __syncwarp();
    }

    // ---- final PV(63) ----
    {
        if (!__all_sync(0xffffffffu, (al0p == 1.f) && (al1p == 1.f))) {
#pragma unroll
            for (int nt = 0; nt < 16; nt++) {
                oacc[nt][0] *= al0p; oacc[nt][1] *= al0p;
                oacc[nt][2] *= al1p; oacc[nt][3] *= al1p;
            }
        }
        const u32 pB = sb + P0_B + (63 & 1) * PBUF_B;
        u32 pa[4][4];
#pragma unroll
        for (int kc = 0; kc < 4; kc++)
            ldsm4(pa[kc][0], pa[kc][1], pa[kc][2], pa[kc][3],
                  pB + ((w * 16 + (l & 15)) * 72 + kc * 16 + (l >> 4) * 8) * 2);
        const u32 vBp = sb + ST_B + (63 % 3) * ST_STR + 8192;
#pragma unroll
        for (int kc = 0; kc < 4; kc++) {
#pragma unroll
            for (int np = 0; np < 8; np++) {
                int chan = cb + 16 * np + (l & 7) + ((l >> 4) & 1) * 8;
                int vchk = kc * 2 + ((l >> 3) & 1);
                u32 v0, v1, v2, v3;
                ldsm4(v0, v1, v2, v3,
                      vBp + chan * 128 + ((vchk ^ (chan & 7)) * 16));
                mma16(oacc[2 * np],     pa[kc], v0, v1);
                mma16(oacc[2 * np + 1], pa[kc], v2, v3);
            }
        }
    }

    // ---- epilogue: out = gamma*O/l + x; two 128-chan phases ----
    const float gm = gamma[0];
    const float g0 = gm / l0s, g1 = gm / l1s;
    const int row0 = 16 * rg + rloc, row1 = row0 + 8;
    float* ts = sm;                 // [cl][row] stride 132
#pragma unroll 1
    for (int ph = 0; ph < 2; ph++) {
        __syncthreads();
        if (chh == ph) {
#pragma unroll
            for (int np = 0; np < 8; np++) {
                int cl0 = 16 * np + 2 * kq;
                int cl1 = 16 * np + 8 + 2 * kq;
                ts[cl0 * 132 + row0]       = oacc[2 * np][0] * g0;
                ts[(cl0 + 1) * 132 + row0] = oacc[2 * np][1] * g0;
                ts[cl0 * 132 + row1]       = oacc[2 * np][2] * g1;
                ts[(cl0 + 1) * 132 + row1] = oacc[2 * np][3] * g1;
                ts[cl1 * 132 + row0]       = oacc[2 * np + 1][0] * g0;
                ts[(cl1 + 1) * 132 + row0] = oacc[2 * np + 1][1] * g0;
                ts[cl1 * 132 + row1]       = oacc[2 * np + 1][2] * g1;
                ts[(cl1 + 1) * 132 + row1] = oacc[2 * np + 1][3] * g1;
            }
        }
        __syncthreads();
#pragma unroll
        for (int it = 0; it < 8; it++) {
            int e = tid + it * 512;
            int c = e >> 5, r4 = e & 31;
            float4 o4 = *(const float4*)(ts + c * 132 + r4 * 4);
            size_t g4 = (size_t)(b * C_ + ph * 128 + c) * 1024 + (i0 >> 2) + r4;
            float4 x4 = ((const float4*)x)[g4];
            o4.x += x4.x; o4.y += x4.y; o4.z += x4.z; o4.w += x4.w;
            ((float4*)out)[g4] = o4;
        }
    }
}

// ---------------------------------------------------------------------------
extern "C" void kernel_launch(void* const* d_in, const int* in_sizes, int n_in,
                              void* d_out, int out_size)
{
    const float* x     = (const float*)d_in[0];
    const float* mask  = (const float*)d_in[1];
    const float* Wq    = (const float*)d_in[2];
    const float* bq    = (const float*)d_in[3];
    const float* Wk    = (const float*)d_in[4];
    const float* bk    = (const float*)d_in[5];
    const float* Wv    = (const float*)d_in[6];
    const float* bv    = (const float*)d_in[7];
    const float* gamma = (const float*)d_in[8];
    float* out = (float*)d_out;

    cudaFuncSetAttribute(attn_kernel,
                         cudaFuncAttributeMaxDynamicSharedMemorySize, A_SMEM_BYTES);

    dim3 pgrid(N_ / 64, 5, B_);
    proj_kernel<<<pgrid, 256>>>(x, mask, Wq, bq, Wk, bk, Wv, bv);

    dim3 agrid(N_ / 128, B_);
    attn_kernel<<<agrid, 512, A_SMEM_BYTES>>>(x, gamma, out);
}